// round 2
// baseline (speedup 1.0000x reference)
#include <cuda_runtime.h>
#include <math.h>

// Problem constants: B=2, T=2048, C=1024, H=16, D=64
// M = B*T = 4096

// Scratch (allocation is forbidden; use device globals)
__device__ float g_qkv[4096 * 3072];   // [B*T, 3C]
__device__ float g_y[4096 * 1024];     // attention output [B*T, C]

// ---------------------------------------------------------------------------
// SGEMM with bias: C[m,n] = sum_k A[m,k] * B[k,n] + bias[n]
// 128x128 tile, BK=8, 256 threads, 8x8 per-thread micro-tile.
// Grid: x = M tiles (fast), y = N tiles.
// Requires M%128==0, N%128==0, K%8==0 (true for all our shapes).
// ---------------------------------------------------------------------------
__global__ __launch_bounds__(256) void sgemm_bias_kernel(
    const float* __restrict__ A, const float* __restrict__ Bw,
    const float* __restrict__ bias, float* __restrict__ C,
    int M, int N, int K)
{
    __shared__ __align__(16) float As[8][128];   // A transposed: [k][m]
    __shared__ __align__(16) float Bs[8][128];   // [k][n]

    const int tid = threadIdx.x;
    const int tx = tid & 15;       // n micro
    const int ty = tid >> 4;       // m micro
    const int m0 = blockIdx.x * 128;
    const int n0 = blockIdx.y * 128;

    float acc[8][8] = {};

    const int arow = tid >> 1;
    const int ak   = (tid & 1) * 4;
    const float* Ap = A + (size_t)(m0 + arow) * K + ak;

    const int brow = tid >> 5;
    const int bcol = (tid & 31) * 4;
    const float* Bp = Bw + (size_t)brow * N + n0 + bcol;

    for (int k0 = 0; k0 < K; k0 += 8) {
        float4 a4 = *(const float4*)(Ap + k0);
        As[ak + 0][arow] = a4.x;
        As[ak + 1][arow] = a4.y;
        As[ak + 2][arow] = a4.z;
        As[ak + 3][arow] = a4.w;

        float4 b4 = *(const float4*)(Bp + (size_t)k0 * N);
        *(float4*)&Bs[brow][bcol] = b4;
        __syncthreads();

        #pragma unroll
        for (int kb = 0; kb < 8; kb++) {
            float ra[8], rb[8];
            *(float4*)&ra[0] = *(const float4*)&As[kb][ty * 8];
            *(float4*)&ra[4] = *(const float4*)&As[kb][ty * 8 + 4];
            *(float4*)&rb[0] = *(const float4*)&Bs[kb][tx * 8];
            *(float4*)&rb[4] = *(const float4*)&Bs[kb][tx * 8 + 4];
            #pragma unroll
            for (int i = 0; i < 8; i++)
                #pragma unroll
                for (int j = 0; j < 8; j++)
                    acc[i][j] += ra[i] * rb[j];
        }
        __syncthreads();
    }

    // Epilogue: add bias, store
    float bv[8];
    #pragma unroll
    for (int j = 0; j < 8; j++) bv[j] = bias[n0 + tx * 8 + j];

    #pragma unroll
    for (int i = 0; i < 8; i++) {
        const int row = m0 + ty * 8 + i;
        float* Cp = C + (size_t)row * N + n0 + tx * 8;
        *(float4*)(Cp + 0) = make_float4(acc[i][0] + bv[0], acc[i][1] + bv[1],
                                         acc[i][2] + bv[2], acc[i][3] + bv[3]);
        *(float4*)(Cp + 4) = make_float4(acc[i][4] + bv[4], acc[i][5] + bv[5],
                                         acc[i][6] + bv[6], acc[i][7] + bv[7]);
    }
}

// ---------------------------------------------------------------------------
// Causal flash attention over qkv scratch.
// Grid: (T/64 q-tiles, H, B). Block: 256 threads (16x16, 4x4 micro-tile).
// Per (b,h,qtile): load 64x64 Q (pre-scaled by 1/sqrt(D)*log2e),
// loop over key tiles kt<=qt: S=QK^T, online softmax (exp2), O += P*V.
// Smem: Qs[64][64] + KPs[64][64] (K^T, then reused for P) + Vs[64][64]
//       = 48 KB exactly (static).
// ---------------------------------------------------------------------------
__global__ __launch_bounds__(256) void attn_kernel(
    const float* __restrict__ qkv, float* __restrict__ y)
{
    __shared__ __align__(16) float Qs[64 * 64];   // [m][d]
    __shared__ __align__(16) float KPs[64 * 64];  // K^T: [d][j]  -> later P: [m][kk]
    __shared__ __align__(16) float Vs[64 * 64];   // [kk][d]

    const int tid = threadIdx.x;
    const int qt = blockIdx.x;
    const int h  = blockIdx.y;
    const int b  = blockIdx.z;
    const int q0 = qt * 64;
    const int tx = tid & 15;       // 4 cols: tx*4..tx*4+3
    const int ty = tid >> 4;       // 4 rows: ty*4..ty*4+3

    const float QSCALE = 0.125f * 1.44269504088896f;  // 1/sqrt(64) * log2(e)

    // Load Q tile, pre-scaled
    const float* qbase = qkv + ((size_t)(b * 2048 + q0)) * 3072 + h * 64;
    for (int f = tid; f < 1024; f += 256) {
        const int r = f >> 4;
        const int dc = (f & 15) * 4;
        float4 v = *(const float4*)(qbase + (size_t)r * 3072 + dc);
        v.x *= QSCALE; v.y *= QSCALE; v.z *= QSCALE; v.w *= QSCALE;
        *(float4*)&Qs[r * 64 + dc] = v;
    }

    float o[4][4] = {};
    float mrow[4], lrow[4];
    #pragma unroll
    for (int i = 0; i < 4; i++) { mrow[i] = -1e30f; lrow[i] = 0.f; }

    const float* kbase = qkv + (size_t)(b * 2048) * 3072 + 1024 + h * 64;
    const float* vbase = kbase + 1024;

    for (int kt = 0; kt <= qt; kt++) {
        // Load K tile transposed -> KPs[d][j]; V tile natural -> Vs[kk][d]
        for (int f = tid; f < 1024; f += 256) {
            const int j = f >> 4;
            const int dc = (f & 15) * 4;
            const size_t rowoff = (size_t)(kt * 64 + j) * 3072 + dc;
            float4 kv = *(const float4*)(kbase + rowoff);
            KPs[(dc + 0) * 64 + j] = kv.x;
            KPs[(dc + 1) * 64 + j] = kv.y;
            KPs[(dc + 2) * 64 + j] = kv.z;
            KPs[(dc + 3) * 64 + j] = kv.w;
            float4 vv = *(const float4*)(vbase + rowoff);
            *(float4*)&Vs[j * 64 + dc] = vv;
        }
        __syncthreads();

        // S = Q K^T  (per-thread 4x4)
        float s[4][4] = {};
        #pragma unroll 8
        for (int d = 0; d < 64; d++) {
            float a0 = Qs[(ty * 4 + 0) * 64 + d];
            float a1 = Qs[(ty * 4 + 1) * 64 + d];
            float a2 = Qs[(ty * 4 + 2) * 64 + d];
            float a3 = Qs[(ty * 4 + 3) * 64 + d];
            float4 bvv = *(const float4*)&KPs[d * 64 + tx * 4];
            s[0][0] += a0 * bvv.x; s[0][1] += a0 * bvv.y; s[0][2] += a0 * bvv.z; s[0][3] += a0 * bvv.w;
            s[1][0] += a1 * bvv.x; s[1][1] += a1 * bvv.y; s[1][2] += a1 * bvv.z; s[1][3] += a1 * bvv.w;
            s[2][0] += a2 * bvv.x; s[2][1] += a2 * bvv.y; s[2][2] += a2 * bvv.z; s[2][3] += a2 * bvv.w;
            s[3][0] += a3 * bvv.x; s[3][1] += a3 * bvv.y; s[3][2] += a3 * bvv.z; s[3][3] += a3 * bvv.w;
        }

        // Causal mask (only needed on the diagonal tile)
        if (kt == qt) {
            #pragma unroll
            for (int i = 0; i < 4; i++)
                #pragma unroll
                for (int j = 0; j < 4; j++)
                    if (tx * 4 + j > ty * 4 + i) s[i][j] = -1e30f;
        }

        // Online softmax update (row stats shared across 16 tx lanes via shfl)
        #pragma unroll
        for (int i = 0; i < 4; i++) {
            float tmax = fmaxf(fmaxf(s[i][0], s[i][1]), fmaxf(s[i][2], s[i][3]));
            tmax = fmaxf(tmax, __shfl_xor_sync(0xffffffffu, tmax, 1));
            tmax = fmaxf(tmax, __shfl_xor_sync(0xffffffffu, tmax, 2));
            tmax = fmaxf(tmax, __shfl_xor_sync(0xffffffffu, tmax, 4));
            tmax = fmaxf(tmax, __shfl_xor_sync(0xffffffffu, tmax, 8));
            const float mnew = fmaxf(mrow[i], tmax);
            const float alpha = exp2f(mrow[i] - mnew);
            float rsum = 0.f;
            #pragma unroll
            for (int j = 0; j < 4; j++) {
                s[i][j] = exp2f(s[i][j] - mnew);
                rsum += s[i][j];
            }
            rsum += __shfl_xor_sync(0xffffffffu, rsum, 1);
            rsum += __shfl_xor_sync(0xffffffffu, rsum, 2);
            rsum += __shfl_xor_sync(0xffffffffu, rsum, 4);
            rsum += __shfl_xor_sync(0xffffffffu, rsum, 8);
            lrow[i] = lrow[i] * alpha + rsum;
            mrow[i] = mnew;
            #pragma unroll
            for (int j = 0; j < 4; j++) o[i][j] *= alpha;
        }

        __syncthreads();  // everyone done reading K^T from KPs

        // Write P into KPs as natural [m][kk]
        #pragma unroll
        for (int i = 0; i < 4; i++)
            *(float4*)&KPs[(ty * 4 + i) * 64 + tx * 4] =
                make_float4(s[i][0], s[i][1], s[i][2], s[i][3]);
        __syncthreads();

        // O += P * V  (reduce over kk)
        #pragma unroll 8
        for (int kk = 0; kk < 64; kk++) {
            float a0 = KPs[(ty * 4 + 0) * 64 + kk];
            float a1 = KPs[(ty * 4 + 1) * 64 + kk];
            float a2 = KPs[(ty * 4 + 2) * 64 + kk];
            float a3 = KPs[(ty * 4 + 3) * 64 + kk];
            float4 bvv = *(const float4*)&Vs[kk * 64 + tx * 4];
            o[0][0] += a0 * bvv.x; o[0][1] += a0 * bvv.y; o[0][2] += a0 * bvv.z; o[0][3] += a0 * bvv.w;
            o[1][0] += a1 * bvv.x; o[1][1] += a1 * bvv.y; o[1][2] += a1 * bvv.z; o[1][3] += a1 * bvv.w;
            o[2][0] += a2 * bvv.x; o[2][1] += a2 * bvv.y; o[2][2] += a2 * bvv.z; o[2][3] += a2 * bvv.w;
            o[3][0] += a3 * bvv.x; o[3][1] += a3 * bvv.y; o[3][2] += a3 * bvv.z; o[3][3] += a3 * bvv.w;
        }
        __syncthreads();  // before next tile overwrites KPs/Vs
    }

    // Normalize and store: y[b, q0+row, h*64 + d]
    #pragma unroll
    for (int i = 0; i < 4; i++) {
        const int row = q0 + ty * 4 + i;
        const float inv = 1.0f / lrow[i];
        float* yp = y + ((size_t)(b * 2048 + row)) * 1024 + h * 64 + tx * 4;
        *(float4*)yp = make_float4(o[i][0] * inv, o[i][1] * inv,
                                   o[i][2] * inv, o[i][3] * inv);
    }
}

// ---------------------------------------------------------------------------
// Launch
// ---------------------------------------------------------------------------
extern "C" void kernel_launch(void* const* d_in, const int* in_sizes, int n_in,
                              void* d_out, int out_size)
{
    const float* x      = (const float*)d_in[0];   // [2,2048,1024]
    const float* w_attn = (const float*)d_in[1];   // [1024,3072]
    const float* b_attn = (const float*)d_in[2];   // [3072]
    const float* w_proj = (const float*)d_in[3];   // [1024,1024]
    const float* b_proj = (const float*)d_in[4];   // [1024]
    float* out = (float*)d_out;                    // [2,2048,1024]

    float* qkv = nullptr;
    float* y   = nullptr;
    cudaGetSymbolAddress((void**)&qkv, g_qkv);
    cudaGetSymbolAddress((void**)&y, g_y);

    // 1) qkv = x @ w_attn + b_attn   (M=4096, N=3072, K=1024)
    sgemm_bias_kernel<<<dim3(4096 / 128, 3072 / 128), 256>>>(
        x, w_attn, b_attn, qkv, 4096, 3072, 1024);

    // 2) causal attention -> y  (grid: qtiles x heads x batch)
    attn_kernel<<<dim3(2048 / 64, 16, 2), 256>>>(qkv, y);

    // 3) out = y @ w_proj + b_proj  (M=4096, N=1024, K=1024)
    sgemm_bias_kernel<<<dim3(4096 / 128, 1024 / 128), 256>>>(
        y, w_proj, b_proj, out, 4096, 1024, 1024);
}

// round 4
// speedup vs baseline: 1.4097x; 1.4097x over previous
#include <cuda_runtime.h>
#include <cuda_bf16.h>
#include <cstdint>
#include <math.h>

// Problem constants: B=2, T=2048, C=1024, H=16, D=64, M = B*T = 4096

// ---------------------------------------------------------------------------
// Scratch (allocation forbidden -> device globals)
// ---------------------------------------------------------------------------
__device__ float g_qkv[4096 * 3072];              // [B*T, 3C] fp32
__device__ float g_y[4096 * 1024];                // attention out fp32
__device__ __nv_bfloat16 g_xh[4096 * 1024];       // x hi/lo
__device__ __nv_bfloat16 g_xl[4096 * 1024];
__device__ __nv_bfloat16 g_wah[3072 * 1024];      // w_attn^T hi/lo  [N,K]
__device__ __nv_bfloat16 g_wal[3072 * 1024];
__device__ __nv_bfloat16 g_wph[1024 * 1024];      // w_proj^T hi/lo  [N,K]
__device__ __nv_bfloat16 g_wpl[1024 * 1024];
__device__ __nv_bfloat16 g_yh[4096 * 1024];       // y hi/lo
__device__ __nv_bfloat16 g_yl[4096 * 1024];

// ---------------------------------------------------------------------------
// PTX helpers (plain sm_100-safe: mma.sync + cp.async only)
// ---------------------------------------------------------------------------
__device__ __forceinline__ uint32_t smem_to_u32(const void* p) {
    uint32_t a;
    asm("{ .reg .u64 t; cvta.to.shared.u64 t, %1; cvt.u32.u64 %0, t; }" : "=r"(a) : "l"(p));
    return a;
}

#define CP_ASYNC16(dst_u32, src_ptr) \
    asm volatile("cp.async.cg.shared.global [%0], [%1], 16;" \
                 :: "r"(dst_u32), "l"(src_ptr) : "memory")
#define CP_COMMIT() asm volatile("cp.async.commit_group;" ::: "memory")
#define CP_WAIT(n)  asm volatile("cp.async.wait_group %0;" :: "n"(n) : "memory")

// mma.sync m16n8k16 row.col f32 += bf16 * bf16
#define MMA_BF16(c, a, b) \
    asm volatile("mma.sync.aligned.m16n8k16.row.col.f32.bf16.bf16.f32 " \
                 "{%0,%1,%2,%3}, {%4,%5,%6,%7}, {%8,%9}, {%0,%1,%2,%3};" \
                 : "+f"((c)[0]), "+f"((c)[1]), "+f"((c)[2]), "+f"((c)[3]) \
                 : "r"((a)[0]), "r"((a)[1]), "r"((a)[2]), "r"((a)[3]), \
                   "r"((b)[0]), "r"((b)[1]))

// ---------------------------------------------------------------------------
// Pre-pass 1: elementwise fp32 -> (hi, lo) bf16 split
// ---------------------------------------------------------------------------
__global__ __launch_bounds__(256) void split_bf16_kernel(
    const float* __restrict__ in, __nv_bfloat16* __restrict__ hi,
    __nv_bfloat16* __restrict__ lo, int n4)
{
    int i = blockIdx.x * 256 + threadIdx.x;
    if (i >= n4) return;
    float4 v = ((const float4*)in)[i];
    __nv_bfloat16 h0 = __float2bfloat16_rn(v.x);
    __nv_bfloat16 h1 = __float2bfloat16_rn(v.y);
    __nv_bfloat16 h2 = __float2bfloat16_rn(v.z);
    __nv_bfloat16 h3 = __float2bfloat16_rn(v.w);
    __nv_bfloat16 l0 = __float2bfloat16_rn(v.x - __bfloat162float(h0));
    __nv_bfloat16 l1 = __float2bfloat16_rn(v.y - __bfloat162float(h1));
    __nv_bfloat16 l2 = __float2bfloat16_rn(v.z - __bfloat162float(h2));
    __nv_bfloat16 l3 = __float2bfloat16_rn(v.w - __bfloat162float(h3));
    ((__nv_bfloat162*)hi)[i * 2 + 0] = __nv_bfloat162(h0, h1);
    ((__nv_bfloat162*)hi)[i * 2 + 1] = __nv_bfloat162(h2, h3);
    ((__nv_bfloat162*)lo)[i * 2 + 0] = __nv_bfloat162(l0, l1);
    ((__nv_bfloat162*)lo)[i * 2 + 1] = __nv_bfloat162(l2, l3);
}

// ---------------------------------------------------------------------------
// Pre-pass 2: W[K,N] fp32 -> W^T[N,K] (hi, lo) bf16. 32x32 tiles.
// Grid: (N/32, K/32), block (32, 8).
// ---------------------------------------------------------------------------
__global__ __launch_bounds__(256) void transpose_split_kernel(
    const float* __restrict__ W, __nv_bfloat16* __restrict__ Th,
    __nv_bfloat16* __restrict__ Tl, int K, int N)
{
    __shared__ float tile[32][33];
    const int n0 = blockIdx.x * 32;
    const int k0 = blockIdx.y * 32;
    const int tx = threadIdx.x, ty = threadIdx.y;
    #pragma unroll
    for (int j = 0; j < 4; j++) {
        int r = ty + j * 8;                       // k_local
        tile[r][tx] = W[(size_t)(k0 + r) * N + n0 + tx];
    }
    __syncthreads();
    #pragma unroll
    for (int j = 0; j < 4; j++) {
        int r = ty + j * 8;                       // n_local
        float v = tile[tx][r];                    // = W[k0+tx][n0+r]
        __nv_bfloat16 h = __float2bfloat16_rn(v);
        __nv_bfloat16 l = __float2bfloat16_rn(v - __bfloat162float(h));
        Th[(size_t)(n0 + r) * K + k0 + tx] = h;
        Tl[(size_t)(n0 + r) * K + k0 + tx] = l;
    }
}

// ---------------------------------------------------------------------------
// Tensor-core GEMM via mma.sync (bf16 hi/lo, fp32 accum):
//   C[M,N] = Ah@Wh^T + Ah@Wl^T + Al@Wh^T + bias
// A* : [M,K] bf16 row-major.  W* : [N,K] bf16 row-major (pre-transposed).
// CTA 128x128, 8 warps (4m x 2n), warp tile 32x64, K-chunk 32,
// cp.async double-buffered smem, pitch 40 bf16 (conflict-free frag loads).
// Dynamic smem: 2 buffers * 4 tiles * 128*40*2B = 81920 bytes.
// ---------------------------------------------------------------------------
#define PITCH 40
#define TILE_BF16 (128 * PITCH)                    // 5120 bf16 per tile
#define BUF_BF16  (4 * TILE_BF16)                  // 20480 bf16 per buffer

__global__ __launch_bounds__(256) void mma_gemm_bias_kernel(
    const __nv_bfloat16* __restrict__ Ah, const __nv_bfloat16* __restrict__ Al,
    const __nv_bfloat16* __restrict__ Wh, const __nv_bfloat16* __restrict__ Wl,
    const float* __restrict__ bias, float* __restrict__ C,
    int M, int N, int K)
{
    extern __shared__ __align__(16) __nv_bfloat16 sm[];
    const uint32_t smem_base = smem_to_u32(sm);
    const int tid = threadIdx.x;
    const int wid = tid >> 5, lane = tid & 31;
    const int wm = wid & 3;                        // warp m: 0..3  -> 32 rows
    const int wn = wid >> 2;                       // warp n: 0..1  -> 64 cols
    const int ra = lane >> 2;                      // 0..7
    const int c2 = (lane & 3) * 2;                 // 0,2,4,6
    const int m0 = blockIdx.x * 128;
    const int n0 = blockIdx.y * 128;

    const __nv_bfloat16* srcs[4] = {
        Ah + (size_t)m0 * K, Al + (size_t)m0 * K,
        Wh + (size_t)n0 * K, Wl + (size_t)n0 * K
    };

    float acc[2][8][4];
    #pragma unroll
    for (int mi = 0; mi < 2; mi++)
        #pragma unroll
        for (int ni = 0; ni < 8; ni++)
            #pragma unroll
            for (int q = 0; q < 4; q++) acc[mi][ni][q] = 0.f;

    const int NCH = K >> 5;                        // K/32 chunks

    // cp.async one chunk (4 tiles x 128 rows x 32 bf16) into buffer `buf`
    auto issue_chunk = [&](int ch, int buf) {
        const int k0 = ch * 32;
        #pragma unroll
        for (int t = 0; t < 4; t++) {
            const __nv_bfloat16* src0 = srcs[t] + k0;
            const uint32_t dst0 = smem_base + (buf * BUF_BF16 + t * TILE_BF16) * 2;
            #pragma unroll
            for (int i = 0; i < 2; i++) {
                int idx = tid + i * 256;           // 0..511
                int row = idx >> 2, seg = idx & 3;
                CP_ASYNC16(dst0 + (row * PITCH + seg * 8) * 2,
                           src0 + (size_t)row * K + seg * 8);
            }
        }
    };

    issue_chunk(0, 0);
    CP_COMMIT();

    for (int ch = 0; ch < NCH; ch++) {
        const int buf = ch & 1;
        if (ch + 1 < NCH) {
            issue_chunk(ch + 1, buf ^ 1);
            CP_COMMIT();
            CP_WAIT(1);
        } else {
            CP_WAIT(0);
        }
        __syncthreads();

        const __nv_bfloat16* Ahs = sm + buf * BUF_BF16;
        const __nv_bfloat16* Als = Ahs + TILE_BF16;
        const __nv_bfloat16* Bhs = Ahs + 2 * TILE_BF16;
        const __nv_bfloat16* Bls = Ahs + 3 * TILE_BF16;

        #pragma unroll
        for (int ks = 0; ks < 2; ks++) {
            const int kofs = ks * 16 + c2;
            uint32_t ah[2][4], al[2][4], bh[8][2], bl[8][2];
            #pragma unroll
            for (int mi = 0; mi < 2; mi++) {
                const int r = wm * 32 + mi * 16 + ra;
                ah[mi][0] = *(const uint32_t*)(Ahs + r * PITCH + kofs);
                ah[mi][1] = *(const uint32_t*)(Ahs + (r + 8) * PITCH + kofs);
                ah[mi][2] = *(const uint32_t*)(Ahs + r * PITCH + kofs + 8);
                ah[mi][3] = *(const uint32_t*)(Ahs + (r + 8) * PITCH + kofs + 8);
                al[mi][0] = *(const uint32_t*)(Als + r * PITCH + kofs);
                al[mi][1] = *(const uint32_t*)(Als + (r + 8) * PITCH + kofs);
                al[mi][2] = *(const uint32_t*)(Als + r * PITCH + kofs + 8);
                al[mi][3] = *(const uint32_t*)(Als + (r + 8) * PITCH + kofs + 8);
            }
            #pragma unroll
            for (int ni = 0; ni < 8; ni++) {
                const int n = wn * 64 + ni * 8 + ra;
                bh[ni][0] = *(const uint32_t*)(Bhs + n * PITCH + kofs);
                bh[ni][1] = *(const uint32_t*)(Bhs + n * PITCH + kofs + 8);
                bl[ni][0] = *(const uint32_t*)(Bls + n * PITCH + kofs);
                bl[ni][1] = *(const uint32_t*)(Bls + n * PITCH + kofs + 8);
            }
            #pragma unroll
            for (int mi = 0; mi < 2; mi++)
                #pragma unroll
                for (int ni = 0; ni < 8; ni++) {
                    MMA_BF16(acc[mi][ni], ah[mi], bh[ni]);
                    MMA_BF16(acc[mi][ni], ah[mi], bl[ni]);
                    MMA_BF16(acc[mi][ni], al[mi], bh[ni]);
                }
        }
        __syncthreads();
    }

    // Epilogue: registers -> gmem with bias (float2 stores)
    #pragma unroll
    for (int ni = 0; ni < 8; ni++) {
        const int col = n0 + wn * 64 + ni * 8 + c2;
        const float bv0 = bias[col], bv1 = bias[col + 1];
        #pragma unroll
        for (int mi = 0; mi < 2; mi++) {
            const int r0 = m0 + wm * 32 + mi * 16 + ra;
            float2* p0 = (float2*)(C + (size_t)r0 * N + col);
            float2* p1 = (float2*)(C + (size_t)(r0 + 8) * N + col);
            *p0 = make_float2(acc[mi][ni][0] + bv0, acc[mi][ni][1] + bv1);
            *p1 = make_float2(acc[mi][ni][2] + bv0, acc[mi][ni][3] + bv1);
        }
    }
}

// ---------------------------------------------------------------------------
// Causal flash attention (unchanged from validated baseline).
// Grid: (T/64, H, B). Block 256. 48KB static smem.
// ---------------------------------------------------------------------------
__global__ __launch_bounds__(256) void attn_kernel(
    const float* __restrict__ qkv, float* __restrict__ y)
{
    __shared__ __align__(16) float Qs[64 * 64];
    __shared__ __align__(16) float KPs[64 * 64];
    __shared__ __align__(16) float Vs[64 * 64];

    const int tid = threadIdx.x;
    const int qt = blockIdx.x;
    const int h  = blockIdx.y;
    const int b  = blockIdx.z;
    const int q0 = qt * 64;
    const int tx = tid & 15;
    const int ty = tid >> 4;

    const float QSCALE = 0.125f * 1.44269504088896f;

    const float* qbase = qkv + ((size_t)(b * 2048 + q0)) * 3072 + h * 64;
    for (int f = tid; f < 1024; f += 256) {
        const int r = f >> 4;
        const int dc = (f & 15) * 4;
        float4 v = *(const float4*)(qbase + (size_t)r * 3072 + dc);
        v.x *= QSCALE; v.y *= QSCALE; v.z *= QSCALE; v.w *= QSCALE;
        *(float4*)&Qs[r * 64 + dc] = v;
    }

    float o[4][4] = {};
    float mrow[4], lrow[4];
    #pragma unroll
    for (int i = 0; i < 4; i++) { mrow[i] = -1e30f; lrow[i] = 0.f; }

    const float* kbase = qkv + (size_t)(b * 2048) * 3072 + 1024 + h * 64;
    const float* vbase = kbase + 1024;

    for (int kt = 0; kt <= qt; kt++) {
        for (int f = tid; f < 1024; f += 256) {
            const int j = f >> 4;
            const int dc = (f & 15) * 4;
            const size_t rowoff = (size_t)(kt * 64 + j) * 3072 + dc;
            float4 kv = *(const float4*)(kbase + rowoff);
            KPs[(dc + 0) * 64 + j] = kv.x;
            KPs[(dc + 1) * 64 + j] = kv.y;
            KPs[(dc + 2) * 64 + j] = kv.z;
            KPs[(dc + 3) * 64 + j] = kv.w;
            float4 vv = *(const float4*)(vbase + rowoff);
            *(float4*)&Vs[j * 64 + dc] = vv;
        }
        __syncthreads();

        float s[4][4] = {};
        #pragma unroll 8
        for (int d = 0; d < 64; d++) {
            float a0 = Qs[(ty * 4 + 0) * 64 + d];
            float a1 = Qs[(ty * 4 + 1) * 64 + d];
            float a2 = Qs[(ty * 4 + 2) * 64 + d];
            float a3 = Qs[(ty * 4 + 3) * 64 + d];
            float4 bvv = *(const float4*)&KPs[d * 64 + tx * 4];
            s[0][0] += a0 * bvv.x; s[0][1] += a0 * bvv.y; s[0][2] += a0 * bvv.z; s[0][3] += a0 * bvv.w;
            s[1][0] += a1 * bvv.x; s[1][1] += a1 * bvv.y; s[1][2] += a1 * bvv.z; s[1][3] += a1 * bvv.w;
            s[2][0] += a2 * bvv.x; s[2][1] += a2 * bvv.y; s[2][2] += a2 * bvv.z; s[2][3] += a2 * bvv.w;
            s[3][0] += a3 * bvv.x; s[3][1] += a3 * bvv.y; s[3][2] += a3 * bvv.z; s[3][3] += a3 * bvv.w;
        }

        if (kt == qt) {
            #pragma unroll
            for (int i = 0; i < 4; i++)
                #pragma unroll
                for (int j = 0; j < 4; j++)
                    if (tx * 4 + j > ty * 4 + i) s[i][j] = -1e30f;
        }

        #pragma unroll
        for (int i = 0; i < 4; i++) {
            float tmax = fmaxf(fmaxf(s[i][0], s[i][1]), fmaxf(s[i][2], s[i][3]));
            tmax = fmaxf(tmax, __shfl_xor_sync(0xffffffffu, tmax, 1));
            tmax = fmaxf(tmax, __shfl_xor_sync(0xffffffffu, tmax, 2));
            tmax = fmaxf(tmax, __shfl_xor_sync(0xffffffffu, tmax, 4));
            tmax = fmaxf(tmax, __shfl_xor_sync(0xffffffffu, tmax, 8));
            const float mnew = fmaxf(mrow[i], tmax);
            const float alpha = exp2f(mrow[i] - mnew);
            float rsum = 0.f;
            #pragma unroll
            for (int j = 0; j < 4; j++) {
                s[i][j] = exp2f(s[i][j] - mnew);
                rsum += s[i][j];
            }
            rsum += __shfl_xor_sync(0xffffffffu, rsum, 1);
            rsum += __shfl_xor_sync(0xffffffffu, rsum, 2);
            rsum += __shfl_xor_sync(0xffffffffu, rsum, 4);
            rsum += __shfl_xor_sync(0xffffffffu, rsum, 8);
            lrow[i] = lrow[i] * alpha + rsum;
            mrow[i] = mnew;
            #pragma unroll
            for (int j = 0; j < 4; j++) o[i][j] *= alpha;
        }

        __syncthreads();

        #pragma unroll
        for (int i = 0; i < 4; i++)
            *(float4*)&KPs[(ty * 4 + i) * 64 + tx * 4] =
                make_float4(s[i][0], s[i][1], s[i][2], s[i][3]);
        __syncthreads();

        #pragma unroll 8
        for (int kk = 0; kk < 64; kk++) {
            float a0 = KPs[(ty * 4 + 0) * 64 + kk];
            float a1 = KPs[(ty * 4 + 1) * 64 + kk];
            float a2 = KPs[(ty * 4 + 2) * 64 + kk];
            float a3 = KPs[(ty * 4 + 3) * 64 + kk];
            float4 bvv = *(const float4*)&Vs[kk * 64 + tx * 4];
            o[0][0] += a0 * bvv.x; o[0][1] += a0 * bvv.y; o[0][2] += a0 * bvv.z; o[0][3] += a0 * bvv.w;
            o[1][0] += a1 * bvv.x; o[1][1] += a1 * bvv.y; o[1][2] += a1 * bvv.z; o[1][3] += a1 * bvv.w;
            o[2][0] += a2 * bvv.x; o[2][1] += a2 * bvv.y; o[2][2] += a2 * bvv.z; o[2][3] += a2 * bvv.w;
            o[3][0] += a3 * bvv.x; o[3][1] += a3 * bvv.y; o[3][2] += a3 * bvv.z; o[3][3] += a3 * bvv.w;
        }
        __syncthreads();
    }

    #pragma unroll
    for (int i = 0; i < 4; i++) {
        const int row = q0 + ty * 4 + i;
        const float inv = 1.0f / lrow[i];
        float* yp = y + ((size_t)(b * 2048 + row)) * 1024 + h * 64 + tx * 4;
        *(float4*)yp = make_float4(o[i][0] * inv, o[i][1] * inv,
                                   o[i][2] * inv, o[i][3] * inv);
    }
}

// ---------------------------------------------------------------------------
// Launch
// ---------------------------------------------------------------------------
extern "C" void kernel_launch(void* const* d_in, const int* in_sizes, int n_in,
                              void* d_out, int out_size)
{
    const float* x      = (const float*)d_in[0];   // [2,2048,1024]
    const float* w_attn = (const float*)d_in[1];   // [1024,3072]
    const float* b_attn = (const float*)d_in[2];   // [3072]
    const float* w_proj = (const float*)d_in[3];   // [1024,1024]
    const float* b_proj = (const float*)d_in[4];   // [1024]
    float* out = (float*)d_out;                    // [2,2048,1024]

    float *qkv, *y;
    __nv_bfloat16 *xh, *xl, *wah, *wal, *wph, *wpl, *yh, *yl;
    cudaGetSymbolAddress((void**)&qkv, g_qkv);
    cudaGetSymbolAddress((void**)&y,   g_y);
    cudaGetSymbolAddress((void**)&xh,  g_xh);
    cudaGetSymbolAddress((void**)&xl,  g_xl);
    cudaGetSymbolAddress((void**)&wah, g_wah);
    cudaGetSymbolAddress((void**)&wal, g_wal);
    cudaGetSymbolAddress((void**)&wph, g_wph);
    cudaGetSymbolAddress((void**)&wpl, g_wpl);
    cudaGetSymbolAddress((void**)&yh,  g_yh);
    cudaGetSymbolAddress((void**)&yl,  g_yl);

    cudaFuncSetAttribute(mma_gemm_bias_kernel,
                         cudaFuncAttributeMaxDynamicSharedMemorySize, 81920);

    // Pre-pass: split x, transpose+split weights
    split_bf16_kernel<<<4096, 256>>>(x, xh, xl, 4096 * 1024 / 4);
    transpose_split_kernel<<<dim3(3072 / 32, 1024 / 32), dim3(32, 8)>>>(
        w_attn, wah, wal, 1024, 3072);
    transpose_split_kernel<<<dim3(1024 / 32, 1024 / 32), dim3(32, 8)>>>(
        w_proj, wph, wpl, 1024, 1024);

    // 1) qkv = x @ w_attn + b_attn   (mma.sync, hi/lo split)
    mma_gemm_bias_kernel<<<dim3(4096 / 128, 3072 / 128), 256, 81920>>>(
        xh, xl, wah, wal, b_attn, qkv, 4096, 3072, 1024);

    // 2) causal attention -> y
    attn_kernel<<<dim3(2048 / 64, 16, 2), 256>>>(qkv, y);

    // 3) split y, then out = y @ w_proj + b_proj
    split_bf16_kernel<<<4096, 256>>>(y, yh, yl, 4096 * 1024 / 4);
    mma_gemm_bias_kernel<<<dim3(4096 / 128, 1024 / 128), 256, 81920>>>(
        yh, yl, wph, wpl, b_proj, out, 4096, 1024, 1024);
}

// round 5
// speedup vs baseline: 2.2816x; 1.6185x over previous
#include <cuda_runtime.h>
#include <cuda_bf16.h>
#include <cstdint>
#include <math.h>

// Problem constants: B=2, T=2048, C=1024, H=16, D=64, M = B*T = 4096

// ---------------------------------------------------------------------------
// Scratch (allocation forbidden -> device globals)
// ---------------------------------------------------------------------------
__device__ float g_qkv[4096 * 3072];              // [B*T, 3C] fp32
__device__ float g_y[4096 * 1024];                // attention out fp32
__device__ __nv_bfloat16 g_xh[4096 * 1024];       // x hi/lo
__device__ __nv_bfloat16 g_xl[4096 * 1024];
__device__ __nv_bfloat16 g_wah[3072 * 1024];      // w_attn^T hi/lo  [N,K]
__device__ __nv_bfloat16 g_wal[3072 * 1024];
__device__ __nv_bfloat16 g_wph[1024 * 1024];      // w_proj^T hi/lo  [N,K]
__device__ __nv_bfloat16 g_wpl[1024 * 1024];
__device__ __nv_bfloat16 g_yh[4096 * 1024];       // y hi/lo
__device__ __nv_bfloat16 g_yl[4096 * 1024];

// ---------------------------------------------------------------------------
// PTX helpers (plain sm_100-safe: mma.sync + cp.async only)
// ---------------------------------------------------------------------------
__device__ __forceinline__ uint32_t smem_to_u32(const void* p) {
    uint32_t a;
    asm("{ .reg .u64 t; cvta.to.shared.u64 t, %1; cvt.u32.u64 %0, t; }" : "=r"(a) : "l"(p));
    return a;
}

#define CP_ASYNC16(dst_u32, src_ptr) \
    asm volatile("cp.async.cg.shared.global [%0], [%1], 16;" \
                 :: "r"(dst_u32), "l"(src_ptr) : "memory")
#define CP_COMMIT() asm volatile("cp.async.commit_group;" ::: "memory")
#define CP_WAIT(n)  asm volatile("cp.async.wait_group %0;" :: "n"(n) : "memory")

// mma.sync m16n8k16 row.col f32 += bf16 * bf16
#define MMA_BF16(c, a, b) \
    asm volatile("mma.sync.aligned.m16n8k16.row.col.f32.bf16.bf16.f32 " \
                 "{%0,%1,%2,%3}, {%4,%5,%6,%7}, {%8,%9}, {%0,%1,%2,%3};" \
                 : "+f"((c)[0]), "+f"((c)[1]), "+f"((c)[2]), "+f"((c)[3]) \
                 : "r"((a)[0]), "r"((a)[1]), "r"((a)[2]), "r"((a)[3]), \
                   "r"((b)[0]), "r"((b)[1]))

// fp32 pair -> (hi, lo) bf16x2 packed in u32
__device__ __forceinline__ void split2(float x, float y, uint32_t& h, uint32_t& l) {
    __nv_bfloat162 h2 = __floats2bfloat162_rn(x, y);
    __nv_bfloat162 l2 = __floats2bfloat162_rn(x - __bfloat162float(h2.x),
                                              y - __bfloat162float(h2.y));
    h = *(uint32_t*)&h2;
    l = *(uint32_t*)&l2;
}

// ---------------------------------------------------------------------------
// Pre-pass 1: elementwise fp32 -> (hi, lo) bf16 split
// ---------------------------------------------------------------------------
__global__ __launch_bounds__(256) void split_bf16_kernel(
    const float* __restrict__ in, __nv_bfloat16* __restrict__ hi,
    __nv_bfloat16* __restrict__ lo, int n4)
{
    int i = blockIdx.x * 256 + threadIdx.x;
    if (i >= n4) return;
    float4 v = ((const float4*)in)[i];
    uint32_t h0, l0, h1, l1;
    split2(v.x, v.y, h0, l0);
    split2(v.z, v.w, h1, l1);
    ((uint32_t*)hi)[i * 2 + 0] = h0;
    ((uint32_t*)hi)[i * 2 + 1] = h1;
    ((uint32_t*)lo)[i * 2 + 0] = l0;
    ((uint32_t*)lo)[i * 2 + 1] = l1;
}

// ---------------------------------------------------------------------------
// Pre-pass 2: W[K,N] fp32 -> W^T[N,K] (hi, lo) bf16. 32x32 tiles.
// Grid: (N/32, K/32), block (32, 8).
// ---------------------------------------------------------------------------
__global__ __launch_bounds__(256) void transpose_split_kernel(
    const float* __restrict__ W, __nv_bfloat16* __restrict__ Th,
    __nv_bfloat16* __restrict__ Tl, int K, int N)
{
    __shared__ float tile[32][33];
    const int n0 = blockIdx.x * 32;
    const int k0 = blockIdx.y * 32;
    const int tx = threadIdx.x, ty = threadIdx.y;
    #pragma unroll
    for (int j = 0; j < 4; j++) {
        int r = ty + j * 8;                       // k_local
        tile[r][tx] = W[(size_t)(k0 + r) * N + n0 + tx];
    }
    __syncthreads();
    #pragma unroll
    for (int j = 0; j < 4; j++) {
        int r = ty + j * 8;                       // n_local
        float v = tile[tx][r];                    // = W[k0+tx][n0+r]
        __nv_bfloat16 h = __float2bfloat16_rn(v);
        __nv_bfloat16 l = __float2bfloat16_rn(v - __bfloat162float(h));
        Th[(size_t)(n0 + r) * K + k0 + tx] = h;
        Tl[(size_t)(n0 + r) * K + k0 + tx] = l;
    }
}

// ---------------------------------------------------------------------------
// Tensor-core GEMM via mma.sync (bf16 hi/lo, fp32 accum):
//   C[M,N] = Ah@Wh^T + Ah@Wl^T + Al@Wh^T + bias
// (unchanged from Round 4 — 45% tensor, 243 TF/s)
// ---------------------------------------------------------------------------
#define PITCH 40
#define TILE_BF16 (128 * PITCH)
#define BUF_BF16  (4 * TILE_BF16)

__global__ __launch_bounds__(256) void mma_gemm_bias_kernel(
    const __nv_bfloat16* __restrict__ Ah, const __nv_bfloat16* __restrict__ Al,
    const __nv_bfloat16* __restrict__ Wh, const __nv_bfloat16* __restrict__ Wl,
    const float* __restrict__ bias, float* __restrict__ C,
    int M, int N, int K)
{
    extern __shared__ __align__(16) __nv_bfloat16 sm[];
    const uint32_t smem_base = smem_to_u32(sm);
    const int tid = threadIdx.x;
    const int wid = tid >> 5, lane = tid & 31;
    const int wm = wid & 3;
    const int wn = wid >> 2;
    const int ra = lane >> 2;
    const int c2 = (lane & 3) * 2;
    const int m0 = blockIdx.x * 128;
    const int n0 = blockIdx.y * 128;

    const __nv_bfloat16* srcs[4] = {
        Ah + (size_t)m0 * K, Al + (size_t)m0 * K,
        Wh + (size_t)n0 * K, Wl + (size_t)n0 * K
    };

    float acc[2][8][4];
    #pragma unroll
    for (int mi = 0; mi < 2; mi++)
        #pragma unroll
        for (int ni = 0; ni < 8; ni++)
            #pragma unroll
            for (int q = 0; q < 4; q++) acc[mi][ni][q] = 0.f;

    const int NCH = K >> 5;

    auto issue_chunk = [&](int ch, int buf) {
        const int k0 = ch * 32;
        #pragma unroll
        for (int t = 0; t < 4; t++) {
            const __nv_bfloat16* src0 = srcs[t] + k0;
            const uint32_t dst0 = smem_base + (buf * BUF_BF16 + t * TILE_BF16) * 2;
            #pragma unroll
            for (int i = 0; i < 2; i++) {
                int idx = tid + i * 256;
                int row = idx >> 2, seg = idx & 3;
                CP_ASYNC16(dst0 + (row * PITCH + seg * 8) * 2,
                           src0 + (size_t)row * K + seg * 8);
            }
        }
    };

    issue_chunk(0, 0);
    CP_COMMIT();

    for (int ch = 0; ch < NCH; ch++) {
        const int buf = ch & 1;
        if (ch + 1 < NCH) {
            issue_chunk(ch + 1, buf ^ 1);
            CP_COMMIT();
            CP_WAIT(1);
        } else {
            CP_WAIT(0);
        }
        __syncthreads();

        const __nv_bfloat16* Ahs = sm + buf * BUF_BF16;
        const __nv_bfloat16* Als = Ahs + TILE_BF16;
        const __nv_bfloat16* Bhs = Ahs + 2 * TILE_BF16;
        const __nv_bfloat16* Bls = Ahs + 3 * TILE_BF16;

        #pragma unroll
        for (int ks = 0; ks < 2; ks++) {
            const int kofs = ks * 16 + c2;
            uint32_t ah[2][4], al[2][4], bh[8][2], bl[8][2];
            #pragma unroll
            for (int mi = 0; mi < 2; mi++) {
                const int r = wm * 32 + mi * 16 + ra;
                ah[mi][0] = *(const uint32_t*)(Ahs + r * PITCH + kofs);
                ah[mi][1] = *(const uint32_t*)(Ahs + (r + 8) * PITCH + kofs);
                ah[mi][2] = *(const uint32_t*)(Ahs + r * PITCH + kofs + 8);
                ah[mi][3] = *(const uint32_t*)(Ahs + (r + 8) * PITCH + kofs + 8);
                al[mi][0] = *(const uint32_t*)(Als + r * PITCH + kofs);
                al[mi][1] = *(const uint32_t*)(Als + (r + 8) * PITCH + kofs);
                al[mi][2] = *(const uint32_t*)(Als + r * PITCH + kofs + 8);
                al[mi][3] = *(const uint32_t*)(Als + (r + 8) * PITCH + kofs + 8);
            }
            #pragma unroll
            for (int ni = 0; ni < 8; ni++) {
                const int n = wn * 64 + ni * 8 + ra;
                bh[ni][0] = *(const uint32_t*)(Bhs + n * PITCH + kofs);
                bh[ni][1] = *(const uint32_t*)(Bhs + n * PITCH + kofs + 8);
                bl[ni][0] = *(const uint32_t*)(Bls + n * PITCH + kofs);
                bl[ni][1] = *(const uint32_t*)(Bls + n * PITCH + kofs + 8);
            }
            #pragma unroll
            for (int mi = 0; mi < 2; mi++)
                #pragma unroll
                for (int ni = 0; ni < 8; ni++) {
                    MMA_BF16(acc[mi][ni], ah[mi], bh[ni]);
                    MMA_BF16(acc[mi][ni], ah[mi], bl[ni]);
                    MMA_BF16(acc[mi][ni], al[mi], bh[ni]);
                }
        }
        __syncthreads();
    }

    #pragma unroll
    for (int ni = 0; ni < 8; ni++) {
        const int col = n0 + wn * 64 + ni * 8 + c2;
        const float bv0 = bias[col], bv1 = bias[col + 1];
        #pragma unroll
        for (int mi = 0; mi < 2; mi++) {
            const int r0 = m0 + wm * 32 + mi * 16 + ra;
            float2* p0 = (float2*)(C + (size_t)r0 * N + col);
            float2* p1 = (float2*)(C + (size_t)(r0 + 8) * N + col);
            *p0 = make_float2(acc[mi][ni][0] + bv0, acc[mi][ni][1] + bv1);
            *p1 = make_float2(acc[mi][ni][2] + bv0, acc[mi][ni][3] + bv1);
        }
    }
}

// ---------------------------------------------------------------------------
// Tensor-core causal flash attention (bf16 hi/lo mma, fp32 softmax).
// CTA: 128 q-rows x 64-key tiles. 8 warps, warp = 16 q-rows.
// smem (bf16, pitch 72): Qh Ql [128][72], Kh Kl [64][72], Vth Vtl [64][72]
//   total 36864 bf16 = 73728 B (dynamic).
// S frag accumulators feed PV A-fragments directly (register reuse).
// ---------------------------------------------------------------------------
#define AP 72                                     // attention smem pitch (bf16)
#define QH_OFF 0
#define QL_OFF 9216
#define KH_OFF 18432
#define KL_OFF 23040
#define VTH_OFF 27648
#define VTL_OFF 32256

__global__ __launch_bounds__(256) void attn_mma_kernel(
    const float* __restrict__ qkv, float* __restrict__ y)
{
    extern __shared__ __align__(16) __nv_bfloat16 sma[];
    const int tid = threadIdx.x;
    const int wid = tid >> 5, lane = tid & 31;
    const int gr = lane >> 2;                     // 0..7
    const int gc = lane & 3;                      // 0..3
    const int qt = gridDim.x - 1 - blockIdx.x;    // heavy CTAs first
    const int h  = blockIdx.y;
    const int b  = blockIdx.z;
    const int wq = wid * 16;                      // warp q-row base (local)

    const float QSCALE = 0.125f * 1.44269504088896f;  // 1/sqrt(64)*log2(e)

    // ---- Load Q tile (128 x 64), pre-scaled, hi/lo split ----
    const float* qbase = qkv + ((size_t)(b * 2048 + qt * 128)) * 3072 + h * 64;
    for (int f = tid; f < 2048; f += 256) {
        const int r = f >> 4;
        const int dc = (f & 15) * 4;
        float4 v = *(const float4*)(qbase + (size_t)r * 3072 + dc);
        v.x *= QSCALE; v.y *= QSCALE; v.z *= QSCALE; v.w *= QSCALE;
        uint32_t h0, l0, h1, l1;
        split2(v.x, v.y, h0, l0);
        split2(v.z, v.w, h1, l1);
        *(uint32_t*)&sma[QH_OFF + r * AP + dc]     = h0;
        *(uint32_t*)&sma[QH_OFF + r * AP + dc + 2] = h1;
        *(uint32_t*)&sma[QL_OFF + r * AP + dc]     = l0;
        *(uint32_t*)&sma[QL_OFF + r * AP + dc + 2] = l1;
    }

    float o[8][4];
    #pragma unroll
    for (int j = 0; j < 8; j++)
        #pragma unroll
        for (int q = 0; q < 4; q++) o[j][q] = 0.f;
    float mrow[2] = {-1e30f, -1e30f};
    float lrow[2] = {0.f, 0.f};

    const float* kbase = qkv + (size_t)(b * 2048) * 3072 + 1024 + h * 64;
    const float* vbase = kbase + 1024;

    const int kt_max = 2 * qt + 1;
    for (int kt = 0; kt <= kt_max; kt++) {
        // ---- Load K (natural) and V (transposed) 64x64 tiles, hi/lo ----
        for (int f = tid; f < 1024; f += 256) {
            const int j = f >> 4;                 // key row 0..63
            const int dc = (f & 15) * 4;
            const size_t rowoff = (size_t)(kt * 64 + j) * 3072 + dc;
            float4 kv = *(const float4*)(kbase + rowoff);
            uint32_t h0, l0, h1, l1;
            split2(kv.x, kv.y, h0, l0);
            split2(kv.z, kv.w, h1, l1);
            *(uint32_t*)&sma[KH_OFF + j * AP + dc]     = h0;
            *(uint32_t*)&sma[KH_OFF + j * AP + dc + 2] = h1;
            *(uint32_t*)&sma[KL_OFF + j * AP + dc]     = l0;
            *(uint32_t*)&sma[KL_OFF + j * AP + dc + 2] = l1;
            float4 vv = *(const float4*)(vbase + rowoff);
            float vs[4] = {vv.x, vv.y, vv.z, vv.w};
            #pragma unroll
            for (int i = 0; i < 4; i++) {
                __nv_bfloat16 vh = __float2bfloat16_rn(vs[i]);
                __nv_bfloat16 vl = __float2bfloat16_rn(vs[i] - __bfloat162float(vh));
                sma[VTH_OFF + (dc + i) * AP + j] = vh;
                sma[VTL_OFF + (dc + i) * AP + j] = vl;
            }
        }
        __syncthreads();

        // ---- S = Q K^T (16x64 per warp), hi/lo 3-product ----
        float s[8][4];
        #pragma unroll
        for (int j = 0; j < 8; j++)
            #pragma unroll
            for (int q = 0; q < 4; q++) s[j][q] = 0.f;

        #pragma unroll
        for (int ks = 0; ks < 4; ks++) {
            const int ko = ks * 16 + 2 * gc;
            uint32_t ah[4], al[4];
            ah[0] = *(const uint32_t*)&sma[QH_OFF + (wq + gr) * AP + ko];
            ah[1] = *(const uint32_t*)&sma[QH_OFF + (wq + gr + 8) * AP + ko];
            ah[2] = *(const uint32_t*)&sma[QH_OFF + (wq + gr) * AP + ko + 8];
            ah[3] = *(const uint32_t*)&sma[QH_OFF + (wq + gr + 8) * AP + ko + 8];
            al[0] = *(const uint32_t*)&sma[QL_OFF + (wq + gr) * AP + ko];
            al[1] = *(const uint32_t*)&sma[QL_OFF + (wq + gr + 8) * AP + ko];
            al[2] = *(const uint32_t*)&sma[QL_OFF + (wq + gr) * AP + ko + 8];
            al[3] = *(const uint32_t*)&sma[QL_OFF + (wq + gr + 8) * AP + ko + 8];
            #pragma unroll
            for (int j = 0; j < 8; j++) {
                uint32_t bh[2], bl[2];
                bh[0] = *(const uint32_t*)&sma[KH_OFF + (j * 8 + gr) * AP + ko];
                bh[1] = *(const uint32_t*)&sma[KH_OFF + (j * 8 + gr) * AP + ko + 8];
                bl[0] = *(const uint32_t*)&sma[KL_OFF + (j * 8 + gr) * AP + ko];
                bl[1] = *(const uint32_t*)&sma[KL_OFF + (j * 8 + gr) * AP + ko + 8];
                MMA_BF16(s[j], ah, bh);
                MMA_BF16(s[j], ah, bl);
                MMA_BF16(s[j], al, bh);
            }
        }

        // ---- Causal mask (diagonal-region tiles only) ----
        if (kt >= 2 * qt) {
            const int row0 = qt * 128 + wq + gr;
            #pragma unroll
            for (int j = 0; j < 8; j++) {
                const int col = kt * 64 + j * 8 + 2 * gc;
                if (col > row0)         s[j][0] = -1e30f;
                if (col + 1 > row0)     s[j][1] = -1e30f;
                if (col > row0 + 8)     s[j][2] = -1e30f;
                if (col + 1 > row0 + 8) s[j][3] = -1e30f;
            }
        }

        // ---- Online softmax (2 rows per thread, reduce over gc group) ----
        #pragma unroll
        for (int i = 0; i < 2; i++) {
            const int q0i = i * 2;
            float mx = -1e30f;
            #pragma unroll
            for (int j = 0; j < 8; j++)
                mx = fmaxf(mx, fmaxf(s[j][q0i], s[j][q0i + 1]));
            mx = fmaxf(mx, __shfl_xor_sync(0xffffffffu, mx, 1));
            mx = fmaxf(mx, __shfl_xor_sync(0xffffffffu, mx, 2));
            const float mnew = fmaxf(mrow[i], mx);
            const float alpha = exp2f(mrow[i] - mnew);
            float rsum = 0.f;
            #pragma unroll
            for (int j = 0; j < 8; j++) {
                s[j][q0i]     = exp2f(s[j][q0i] - mnew);
                s[j][q0i + 1] = exp2f(s[j][q0i + 1] - mnew);
                rsum += s[j][q0i] + s[j][q0i + 1];
            }
            rsum += __shfl_xor_sync(0xffffffffu, rsum, 1);
            rsum += __shfl_xor_sync(0xffffffffu, rsum, 2);
            lrow[i] = lrow[i] * alpha + rsum;
            mrow[i] = mnew;
            #pragma unroll
            for (int j = 0; j < 8; j++) {
                o[j][q0i]     *= alpha;
                o[j][q0i + 1] *= alpha;
            }
        }

        // ---- Pack P hi/lo A-fragments (register reuse of S frags) ----
        uint32_t pha[4][4], pla[4][4];
        #pragma unroll
        for (int t = 0; t < 4; t++) {
            split2(s[2 * t][0],     s[2 * t][1],     pha[t][0], pla[t][0]);
            split2(s[2 * t][2],     s[2 * t][3],     pha[t][1], pla[t][1]);
            split2(s[2 * t + 1][0], s[2 * t + 1][1], pha[t][2], pla[t][2]);
            split2(s[2 * t + 1][2], s[2 * t + 1][3], pha[t][3], pla[t][3]);
        }

        // ---- O += P V  (B = V^T from smem) ----
        #pragma unroll
        for (int t = 0; t < 4; t++) {
            const int kk = t * 16 + 2 * gc;
            #pragma unroll
            for (int j = 0; j < 8; j++) {
                uint32_t bvh[2], bvl[2];
                bvh[0] = *(const uint32_t*)&sma[VTH_OFF + (j * 8 + gr) * AP + kk];
                bvh[1] = *(const uint32_t*)&sma[VTH_OFF + (j * 8 + gr) * AP + kk + 8];
                bvl[0] = *(const uint32_t*)&sma[VTL_OFF + (j * 8 + gr) * AP + kk];
                bvl[1] = *(const uint32_t*)&sma[VTL_OFF + (j * 8 + gr) * AP + kk + 8];
                MMA_BF16(o[j], pha[t], bvh);
                MMA_BF16(o[j], pha[t], bvl);
                MMA_BF16(o[j], pla[t], bvh);
            }
        }
        __syncthreads();
    }

    // ---- Epilogue: normalize, store fp32 ----
    const float inv0 = 1.0f / lrow[0];
    const float inv1 = 1.0f / lrow[1];
    const int row0 = b * 2048 + qt * 128 + wq + gr;
    #pragma unroll
    for (int j = 0; j < 8; j++) {
        const int col = h * 64 + j * 8 + 2 * gc;
        *(float2*)(y + (size_t)row0 * 1024 + col) =
            make_float2(o[j][0] * inv0, o[j][1] * inv0);
        *(float2*)(y + (size_t)(row0 + 8) * 1024 + col) =
            make_float2(o[j][2] * inv1, o[j][3] * inv1);
    }
}

// ---------------------------------------------------------------------------
// Launch
// ---------------------------------------------------------------------------
extern "C" void kernel_launch(void* const* d_in, const int* in_sizes, int n_in,
                              void* d_out, int out_size)
{
    const float* x      = (const float*)d_in[0];   // [2,2048,1024]
    const float* w_attn = (const float*)d_in[1];   // [1024,3072]
    const float* b_attn = (const float*)d_in[2];   // [3072]
    const float* w_proj = (const float*)d_in[3];   // [1024,1024]
    const float* b_proj = (const float*)d_in[4];   // [1024]
    float* out = (float*)d_out;                    // [2,2048,1024]

    float *qkv, *y;
    __nv_bfloat16 *xh, *xl, *wah, *wal, *wph, *wpl, *yh, *yl;
    cudaGetSymbolAddress((void**)&qkv, g_qkv);
    cudaGetSymbolAddress((void**)&y,   g_y);
    cudaGetSymbolAddress((void**)&xh,  g_xh);
    cudaGetSymbolAddress((void**)&xl,  g_xl);
    cudaGetSymbolAddress((void**)&wah, g_wah);
    cudaGetSymbolAddress((void**)&wal, g_wal);
    cudaGetSymbolAddress((void**)&wph, g_wph);
    cudaGetSymbolAddress((void**)&wpl, g_wpl);
    cudaGetSymbolAddress((void**)&yh,  g_yh);
    cudaGetSymbolAddress((void**)&yl,  g_yl);

    cudaFuncSetAttribute(mma_gemm_bias_kernel,
                         cudaFuncAttributeMaxDynamicSharedMemorySize, 81920);
    cudaFuncSetAttribute(attn_mma_kernel,
                         cudaFuncAttributeMaxDynamicSharedMemorySize, 73728);

    // Pre-pass: split x, transpose+split weights
    split_bf16_kernel<<<4096, 256>>>(x, xh, xl, 4096 * 1024 / 4);
    transpose_split_kernel<<<dim3(3072 / 32, 1024 / 32), dim3(32, 8)>>>(
        w_attn, wah, wal, 1024, 3072);
    transpose_split_kernel<<<dim3(1024 / 32, 1024 / 32), dim3(32, 8)>>>(
        w_proj, wph, wpl, 1024, 1024);

    // 1) qkv = x @ w_attn + b_attn   (mma.sync, hi/lo split)
    mma_gemm_bias_kernel<<<dim3(4096 / 128, 3072 / 128), 256, 81920>>>(
        xh, xl, wah, wal, b_attn, qkv, 4096, 3072, 1024);

    // 2) causal attention -> y  (tensor cores)
    attn_mma_kernel<<<dim3(2048 / 128, 16, 2), 256, 73728>>>(qkv, y);

    // 3) split y, then out = y @ w_proj + b_proj
    split_bf16_kernel<<<4096, 256>>>(y, yh, yl, 4096 * 1024 / 4);
    mma_gemm_bias_kernel<<<dim3(4096 / 128, 1024 / 128), 256, 81920>>>(
        yh, yl, wph, wpl, b_proj, out, 4096, 1024, 1024);
}

// round 6
// speedup vs baseline: 2.5048x; 1.0978x over previous
#include <cuda_runtime.h>
#include <cuda_bf16.h>
#include <cstdint>
#include <math.h>

// Problem constants: B=2, T=2048, C=1024, H=16, D=64, M = B*T = 4096

// ---------------------------------------------------------------------------
// Scratch (allocation forbidden -> device globals)
// ---------------------------------------------------------------------------
__device__ __nv_bfloat16 g_qkvh[4096 * 3072];     // qkv hi/lo bf16
__device__ __nv_bfloat16 g_qkvl[4096 * 3072];
__device__ __nv_bfloat16 g_xh[4096 * 1024];       // x hi/lo
__device__ __nv_bfloat16 g_xl[4096 * 1024];
__device__ __nv_bfloat16 g_wah[3072 * 1024];      // w_attn^T hi/lo  [N,K]
__device__ __nv_bfloat16 g_wal[3072 * 1024];
__device__ __nv_bfloat16 g_wph[1024 * 1024];      // w_proj^T hi/lo  [N,K]
__device__ __nv_bfloat16 g_wpl[1024 * 1024];
__device__ __nv_bfloat16 g_yh[4096 * 1024];       // attention out hi/lo
__device__ __nv_bfloat16 g_yl[4096 * 1024];

// ---------------------------------------------------------------------------
// PTX helpers (plain sm_100-safe: mma.sync + cp.async + ldmatrix)
// ---------------------------------------------------------------------------
__device__ __forceinline__ uint32_t smem_to_u32(const void* p) {
    uint32_t a;
    asm("{ .reg .u64 t; cvta.to.shared.u64 t, %1; cvt.u32.u64 %0, t; }" : "=r"(a) : "l"(p));
    return a;
}

#define CP_ASYNC16(dst_u32, src_ptr) \
    asm volatile("cp.async.cg.shared.global [%0], [%1], 16;" \
                 :: "r"(dst_u32), "l"(src_ptr) : "memory")
#define CP_COMMIT() asm volatile("cp.async.commit_group;" ::: "memory")
#define CP_WAIT(n)  asm volatile("cp.async.wait_group %0;" :: "n"(n) : "memory")

#define LDSM_X4(r0, r1, r2, r3, addr) \
    asm volatile("ldmatrix.sync.aligned.m8n8.x4.shared.b16 {%0,%1,%2,%3}, [%4];" \
                 : "=r"(r0), "=r"(r1), "=r"(r2), "=r"(r3) : "r"(addr))

// mma.sync m16n8k16 row.col f32 += bf16 * bf16
#define MMA_BF16(c, a, b) \
    asm volatile("mma.sync.aligned.m16n8k16.row.col.f32.bf16.bf16.f32 " \
                 "{%0,%1,%2,%3}, {%4,%5,%6,%7}, {%8,%9}, {%0,%1,%2,%3};" \
                 : "+f"((c)[0]), "+f"((c)[1]), "+f"((c)[2]), "+f"((c)[3]) \
                 : "r"((a)[0]), "r"((a)[1]), "r"((a)[2]), "r"((a)[3]), \
                   "r"((b)[0]), "r"((b)[1]))

// fp32 pair -> (hi, lo) bf16x2 packed in u32
__device__ __forceinline__ void split2(float x, float y, uint32_t& h, uint32_t& l) {
    __nv_bfloat162 h2 = __floats2bfloat162_rn(x, y);
    __nv_bfloat162 l2 = __floats2bfloat162_rn(x - __bfloat162float(h2.x),
                                              y - __bfloat162float(h2.y));
    h = *(uint32_t*)&h2;
    l = *(uint32_t*)&l2;
}

// ---------------------------------------------------------------------------
// Pre-pass 1: elementwise fp32 -> (hi, lo) bf16 split
// ---------------------------------------------------------------------------
__global__ __launch_bounds__(256) void split_bf16_kernel(
    const float* __restrict__ in, __nv_bfloat16* __restrict__ hi,
    __nv_bfloat16* __restrict__ lo, int n4)
{
    int i = blockIdx.x * 256 + threadIdx.x;
    if (i >= n4) return;
    float4 v = ((const float4*)in)[i];
    uint32_t h0, l0, h1, l1;
    split2(v.x, v.y, h0, l0);
    split2(v.z, v.w, h1, l1);
    ((uint32_t*)hi)[i * 2 + 0] = h0;
    ((uint32_t*)hi)[i * 2 + 1] = h1;
    ((uint32_t*)lo)[i * 2 + 0] = l0;
    ((uint32_t*)lo)[i * 2 + 1] = l1;
}

// ---------------------------------------------------------------------------
// Pre-pass 2: W[K,N] fp32 -> W^T[N,K] (hi, lo) bf16. 32x32 tiles.
// ---------------------------------------------------------------------------
__global__ __launch_bounds__(256) void transpose_split_kernel(
    const float* __restrict__ W, __nv_bfloat16* __restrict__ Th,
    __nv_bfloat16* __restrict__ Tl, int K, int N)
{
    __shared__ float tile[32][33];
    const int n0 = blockIdx.x * 32;
    const int k0 = blockIdx.y * 32;
    const int tx = threadIdx.x, ty = threadIdx.y;
    #pragma unroll
    for (int j = 0; j < 4; j++) {
        int r = ty + j * 8;
        tile[r][tx] = W[(size_t)(k0 + r) * N + n0 + tx];
    }
    __syncthreads();
    #pragma unroll
    for (int j = 0; j < 4; j++) {
        int r = ty + j * 8;
        float v = tile[tx][r];
        __nv_bfloat16 h = __float2bfloat16_rn(v);
        __nv_bfloat16 l = __float2bfloat16_rn(v - __bfloat162float(h));
        Th[(size_t)(n0 + r) * K + k0 + tx] = h;
        Tl[(size_t)(n0 + r) * K + k0 + tx] = l;
    }
}

// ---------------------------------------------------------------------------
// Tensor-core GEMM via mma.sync + ldmatrix (bf16 hi/lo, fp32 accum):
//   C = Ah@Wh^T + Ah@Wl^T + Al@Wh^T + bias
// Output: fp32 (Cf) or hi/lo bf16 (Ch/Cl) when Ch != nullptr.
// CTA 128x128, 8 warps (4m x 2n), K-chunk 32, cp.async double buffer.
// ---------------------------------------------------------------------------
#define PITCH 40
#define TILE_BF16 (128 * PITCH)
#define BUF_BF16  (4 * TILE_BF16)

__global__ __launch_bounds__(256) void mma_gemm_kernel(
    const __nv_bfloat16* __restrict__ Ah, const __nv_bfloat16* __restrict__ Al,
    const __nv_bfloat16* __restrict__ Wh, const __nv_bfloat16* __restrict__ Wl,
    const float* __restrict__ bias, float* __restrict__ Cf,
    __nv_bfloat16* __restrict__ Ch, __nv_bfloat16* __restrict__ Cl,
    int M, int N, int K)
{
    extern __shared__ __align__(16) __nv_bfloat16 sm[];
    const uint32_t sbase = smem_to_u32(sm);
    const int tid = threadIdx.x;
    const int wid = tid >> 5, lane = tid & 31;
    const int wm = wid & 3;
    const int wn = wid >> 2;
    const int ra = lane >> 2;
    const int c2 = (lane & 3) * 2;
    const int m0 = blockIdx.x * 128;
    const int n0 = blockIdx.y * 128;

    // ldmatrix per-lane geometry
    const int r8 = lane & 7;
    const int s0 = (lane >> 3) & 1;               // sel&1
    const int s1 = (lane >> 4) & 1;               // sel>>1
    const int rA = r8 + s0 * 8;                   // A row delta
    const int kA = s1 * 8;                        // A k delta
    const int rB = r8 + s1 * 8;                   // B row delta
    const int kB = s0 * 8;                        // B k delta

    const __nv_bfloat16* srcs[4] = {
        Ah + (size_t)m0 * K, Al + (size_t)m0 * K,
        Wh + (size_t)n0 * K, Wl + (size_t)n0 * K
    };

    float acc[2][8][4];
    #pragma unroll
    for (int mi = 0; mi < 2; mi++)
        #pragma unroll
        for (int ni = 0; ni < 8; ni++)
            #pragma unroll
            for (int q = 0; q < 4; q++) acc[mi][ni][q] = 0.f;

    const int NCH = K >> 5;

    auto issue_chunk = [&](int ch, int buf) {
        const int k0 = ch * 32;
        #pragma unroll
        for (int t = 0; t < 4; t++) {
            const __nv_bfloat16* src0 = srcs[t] + k0;
            const uint32_t dst0 = sbase + (buf * BUF_BF16 + t * TILE_BF16) * 2;
            #pragma unroll
            for (int i = 0; i < 2; i++) {
                int idx = tid + i * 256;
                int row = idx >> 2, seg = idx & 3;
                CP_ASYNC16(dst0 + (row * PITCH + seg * 8) * 2,
                           src0 + (size_t)row * K + seg * 8);
            }
        }
    };

    issue_chunk(0, 0);
    CP_COMMIT();

    for (int ch = 0; ch < NCH; ch++) {
        const int buf = ch & 1;
        if (ch + 1 < NCH) {
            issue_chunk(ch + 1, buf ^ 1);
            CP_COMMIT();
            CP_WAIT(1);
        } else {
            CP_WAIT(0);
        }
        __syncthreads();

        const uint32_t boff = sbase + buf * BUF_BF16 * 2;
        #pragma unroll
        for (int ks = 0; ks < 2; ks++) {
            uint32_t ah[2][4], al[2][4], bh[8][2], bl[8][2];
            #pragma unroll
            for (int mi = 0; mi < 2; mi++) {
                const int row = wm * 32 + mi * 16 + rA;
                const uint32_t adr = boff + (row * PITCH + ks * 16 + kA) * 2;
                LDSM_X4(ah[mi][0], ah[mi][1], ah[mi][2], ah[mi][3], adr);
                LDSM_X4(al[mi][0], al[mi][1], al[mi][2], al[mi][3],
                        adr + TILE_BF16 * 2);
            }
            #pragma unroll
            for (int np = 0; np < 4; np++) {
                const int row = wn * 64 + np * 16 + rB;
                const uint32_t adr = boff + 2 * TILE_BF16 * 2 +
                                     (row * PITCH + ks * 16 + kB) * 2;
                LDSM_X4(bh[2 * np][0], bh[2 * np][1],
                        bh[2 * np + 1][0], bh[2 * np + 1][1], adr);
                LDSM_X4(bl[2 * np][0], bl[2 * np][1],
                        bl[2 * np + 1][0], bl[2 * np + 1][1],
                        adr + TILE_BF16 * 2);
            }
            #pragma unroll
            for (int mi = 0; mi < 2; mi++)
                #pragma unroll
                for (int ni = 0; ni < 8; ni++) {
                    MMA_BF16(acc[mi][ni], ah[mi], bh[ni]);
                    MMA_BF16(acc[mi][ni], ah[mi], bl[ni]);
                    MMA_BF16(acc[mi][ni], al[mi], bh[ni]);
                }
        }
        __syncthreads();
    }

    // Epilogue
    #pragma unroll
    for (int ni = 0; ni < 8; ni++) {
        const int col = n0 + wn * 64 + ni * 8 + c2;
        const float bv0 = bias[col], bv1 = bias[col + 1];
        #pragma unroll
        for (int mi = 0; mi < 2; mi++) {
            const int r0 = m0 + wm * 32 + mi * 16 + ra;
            const float v00 = acc[mi][ni][0] + bv0, v01 = acc[mi][ni][1] + bv1;
            const float v10 = acc[mi][ni][2] + bv0, v11 = acc[mi][ni][3] + bv1;
            if (Ch) {
                uint32_t h0, l0, h1, l1;
                split2(v00, v01, h0, l0);
                split2(v10, v11, h1, l1);
                *(uint32_t*)(Ch + (size_t)r0 * N + col) = h0;
                *(uint32_t*)(Cl + (size_t)r0 * N + col) = l0;
                *(uint32_t*)(Ch + (size_t)(r0 + 8) * N + col) = h1;
                *(uint32_t*)(Cl + (size_t)(r0 + 8) * N + col) = l1;
            } else {
                *(float2*)(Cf + (size_t)r0 * N + col) = make_float2(v00, v01);
                *(float2*)(Cf + (size_t)(r0 + 8) * N + col) = make_float2(v10, v11);
            }
        }
    }
}

// ---------------------------------------------------------------------------
// Tensor-core causal flash attention (bf16 hi/lo in gmem, ldmatrix frags).
// CTA: 128 q-rows x 64-key tiles. 8 warps, warp = 16 q-rows.
// smem (bf16, pitch 72): Qh Ql [128][72], Kh Kl [64][72], Vth Vtl [64][72]
// Scale 1/sqrt(D)*log2e applied to S post-mma. Output written hi/lo bf16.
// ---------------------------------------------------------------------------
#define AP 72
#define QH_OFF 0
#define QL_OFF 9216
#define KH_OFF 18432
#define KL_OFF 23040
#define VTH_OFF 27648
#define VTL_OFF 32256

__global__ __launch_bounds__(256) void attn_mma_kernel(
    const __nv_bfloat16* __restrict__ qh, const __nv_bfloat16* __restrict__ ql,
    __nv_bfloat16* __restrict__ yh, __nv_bfloat16* __restrict__ yl)
{
    extern __shared__ __align__(16) __nv_bfloat16 sma[];
    const uint32_t sbase = smem_to_u32(sma);
    const int tid = threadIdx.x;
    const int wid = tid >> 5, lane = tid & 31;
    const int gr = lane >> 2;
    const int gc = lane & 3;
    const int qt = gridDim.x - 1 - blockIdx.x;    // heavy CTAs first
    const int h  = blockIdx.y;
    const int b  = blockIdx.z;
    const int wq = wid * 16;

    // ldmatrix per-lane geometry (same derivation as GEMM)
    const int r8 = lane & 7;
    const int s0 = (lane >> 3) & 1;
    const int s1 = (lane >> 4) & 1;
    const int rA = r8 + s0 * 8, kA = s1 * 8;
    const int rB = r8 + s1 * 8, kB = s0 * 8;

    const float SSCALE = 0.125f * 1.44269504088896f;  // 1/sqrt(64)*log2(e)

    // ---- Load Q tile (128 x 64 bf16 hi/lo) ----
    {
        const size_t qrow = (size_t)(b * 2048 + qt * 128) * 3072 + h * 64;
        #pragma unroll
        for (int i = 0; i < 4; i++) {
            int f = tid + i * 256;                // 0..1023
            int r = f >> 3, seg = f & 7;
            const size_t off = qrow + (size_t)r * 3072 + seg * 8;
            *(uint4*)&sma[QH_OFF + r * AP + seg * 8] = *(const uint4*)(qh + off);
            *(uint4*)&sma[QL_OFF + r * AP + seg * 8] = *(const uint4*)(ql + off);
        }
    }

    float o[8][4];
    #pragma unroll
    for (int j = 0; j < 8; j++)
        #pragma unroll
        for (int q = 0; q < 4; q++) o[j][q] = 0.f;
    float mrow[2] = {-1e30f, -1e30f};
    float lrow[2] = {0.f, 0.f};

    const size_t kcol = (size_t)(b * 2048) * 3072 + 1024 + h * 64;
    const size_t vcol = kcol + 1024;

    const int kt_max = 2 * qt + 1;
    for (int kt = 0; kt <= kt_max; kt++) {
        // ---- Load K (natural) and V (transposed) 64x64 tiles ----
        #pragma unroll
        for (int i = 0; i < 2; i++) {
            int f = tid + i * 256;                // 0..511
            int j = f >> 3, seg = f & 7;
            const size_t off = kcol + (size_t)(kt * 64 + j) * 3072 + seg * 8;
            *(uint4*)&sma[KH_OFF + j * AP + seg * 8] = *(const uint4*)(qh + off);
            *(uint4*)&sma[KL_OFF + j * AP + seg * 8] = *(const uint4*)(ql + off);
            const size_t voff = vcol + (size_t)(kt * 64 + j) * 3072 + seg * 8;
            uint4 vvh = *(const uint4*)(qh + voff);
            uint4 vvl = *(const uint4*)(ql + voff);
            const __nv_bfloat16* ph = (const __nv_bfloat16*)&vvh;
            const __nv_bfloat16* pl = (const __nv_bfloat16*)&vvl;
            #pragma unroll
            for (int e = 0; e < 8; e++) {
                sma[VTH_OFF + (seg * 8 + e) * AP + j] = ph[e];
                sma[VTL_OFF + (seg * 8 + e) * AP + j] = pl[e];
            }
        }
        __syncthreads();

        // ---- S = Q K^T (16x64 per warp), hi/lo 3-product, ldmatrix frags ----
        float s[8][4];
        #pragma unroll
        for (int j = 0; j < 8; j++)
            #pragma unroll
            for (int q = 0; q < 4; q++) s[j][q] = 0.f;

        #pragma unroll
        for (int ks = 0; ks < 4; ks++) {
            uint32_t ah[4], al[4], bh[8][2], bl[8][2];
            {
                const uint32_t adr = sbase +
                    (QH_OFF + (wq + rA) * AP + ks * 16 + kA) * 2;
                LDSM_X4(ah[0], ah[1], ah[2], ah[3], adr);
                LDSM_X4(al[0], al[1], al[2], al[3],
                        adr + (QL_OFF - QH_OFF) * 2);
            }
            #pragma unroll
            for (int np = 0; np < 4; np++) {
                const uint32_t adr = sbase +
                    (KH_OFF + (np * 16 + rB) * AP + ks * 16 + kB) * 2;
                LDSM_X4(bh[2 * np][0], bh[2 * np][1],
                        bh[2 * np + 1][0], bh[2 * np + 1][1], adr);
                LDSM_X4(bl[2 * np][0], bl[2 * np][1],
                        bl[2 * np + 1][0], bl[2 * np + 1][1],
                        adr + (KL_OFF - KH_OFF) * 2);
            }
            #pragma unroll
            for (int j = 0; j < 8; j++) {
                MMA_BF16(s[j], ah, bh[j]);
                MMA_BF16(s[j], ah, bl[j]);
                MMA_BF16(s[j], al, bh[j]);
            }
        }

        // ---- Scale + causal mask ----
        #pragma unroll
        for (int j = 0; j < 8; j++)
            #pragma unroll
            for (int q = 0; q < 4; q++) s[j][q] *= SSCALE;

        if (kt >= 2 * qt) {
            const int row0 = qt * 128 + wq + gr;
            #pragma unroll
            for (int j = 0; j < 8; j++) {
                const int col = kt * 64 + j * 8 + 2 * gc;
                if (col > row0)         s[j][0] = -1e30f;
                if (col + 1 > row0)     s[j][1] = -1e30f;
                if (col > row0 + 8)     s[j][2] = -1e30f;
                if (col + 1 > row0 + 8) s[j][3] = -1e30f;
            }
        }

        // ---- Online softmax (2 rows per thread, reduce over gc group) ----
        #pragma unroll
        for (int i = 0; i < 2; i++) {
            const int q0i = i * 2;
            float mx = -1e30f;
            #pragma unroll
            for (int j = 0; j < 8; j++)
                mx = fmaxf(mx, fmaxf(s[j][q0i], s[j][q0i + 1]));
            mx = fmaxf(mx, __shfl_xor_sync(0xffffffffu, mx, 1));
            mx = fmaxf(mx, __shfl_xor_sync(0xffffffffu, mx, 2));
            const float mnew = fmaxf(mrow[i], mx);
            const float alpha = exp2f(mrow[i] - mnew);
            float rsum = 0.f;
            #pragma unroll
            for (int j = 0; j < 8; j++) {
                s[j][q0i]     = exp2f(s[j][q0i] - mnew);
                s[j][q0i + 1] = exp2f(s[j][q0i + 1] - mnew);
                rsum += s[j][q0i] + s[j][q0i + 1];
            }
            rsum += __shfl_xor_sync(0xffffffffu, rsum, 1);
            rsum += __shfl_xor_sync(0xffffffffu, rsum, 2);
            lrow[i] = lrow[i] * alpha + rsum;
            mrow[i] = mnew;
            #pragma unroll
            for (int j = 0; j < 8; j++) {
                o[j][q0i]     *= alpha;
                o[j][q0i + 1] *= alpha;
            }
        }

        // ---- Pack P hi/lo A-fragments (register reuse of S frags) ----
        uint32_t pha[4][4], pla[4][4];
        #pragma unroll
        for (int t = 0; t < 4; t++) {
            split2(s[2 * t][0],     s[2 * t][1],     pha[t][0], pla[t][0]);
            split2(s[2 * t][2],     s[2 * t][3],     pha[t][1], pla[t][1]);
            split2(s[2 * t + 1][0], s[2 * t + 1][1], pha[t][2], pla[t][2]);
            split2(s[2 * t + 1][2], s[2 * t + 1][3], pha[t][3], pla[t][3]);
        }

        // ---- O += P V  (B = V^T, ldmatrix frags) ----
        #pragma unroll
        for (int t = 0; t < 4; t++) {
            uint32_t bvh[8][2], bvl[8][2];
            #pragma unroll
            for (int np = 0; np < 4; np++) {
                const uint32_t adr = sbase +
                    (VTH_OFF + (np * 16 + rB) * AP + t * 16 + kB) * 2;
                LDSM_X4(bvh[2 * np][0], bvh[2 * np][1],
                        bvh[2 * np + 1][0], bvh[2 * np + 1][1], adr);
                LDSM_X4(bvl[2 * np][0], bvl[2 * np][1],
                        bvl[2 * np + 1][0], bvl[2 * np + 1][1],
                        adr + (VTL_OFF - VTH_OFF) * 2);
            }
            #pragma unroll
            for (int j = 0; j < 8; j++) {
                MMA_BF16(o[j], pha[t], bvh[j]);
                MMA_BF16(o[j], pha[t], bvl[j]);
                MMA_BF16(o[j], pla[t], bvh[j]);
            }
        }
        __syncthreads();
    }

    // ---- Epilogue: normalize, hi/lo split, store bf16 ----
    const float inv0 = 1.0f / lrow[0];
    const float inv1 = 1.0f / lrow[1];
    const int row0 = b * 2048 + qt * 128 + wq + gr;
    #pragma unroll
    for (int j = 0; j < 8; j++) {
        const int col = h * 64 + j * 8 + 2 * gc;
        uint32_t h0, l0, h1, l1;
        split2(o[j][0] * inv0, o[j][1] * inv0, h0, l0);
        split2(o[j][2] * inv1, o[j][3] * inv1, h1, l1);
        *(uint32_t*)(yh + (size_t)row0 * 1024 + col) = h0;
        *(uint32_t*)(yl + (size_t)row0 * 1024 + col) = l0;
        *(uint32_t*)(yh + (size_t)(row0 + 8) * 1024 + col) = h1;
        *(uint32_t*)(yl + (size_t)(row0 + 8) * 1024 + col) = l1;
    }
}

// ---------------------------------------------------------------------------
// Launch
// ---------------------------------------------------------------------------
extern "C" void kernel_launch(void* const* d_in, const int* in_sizes, int n_in,
                              void* d_out, int out_size)
{
    const float* x      = (const float*)d_in[0];   // [2,2048,1024]
    const float* w_attn = (const float*)d_in[1];   // [1024,3072]
    const float* b_attn = (const float*)d_in[2];   // [3072]
    const float* w_proj = (const float*)d_in[3];   // [1024,1024]
    const float* b_proj = (const float*)d_in[4];   // [1024]
    float* out = (float*)d_out;                    // [2,2048,1024]

    __nv_bfloat16 *qkvh, *qkvl, *xh, *xl, *wah, *wal, *wph, *wpl, *yh, *yl;
    cudaGetSymbolAddress((void**)&qkvh, g_qkvh);
    cudaGetSymbolAddress((void**)&qkvl, g_qkvl);
    cudaGetSymbolAddress((void**)&xh,  g_xh);
    cudaGetSymbolAddress((void**)&xl,  g_xl);
    cudaGetSymbolAddress((void**)&wah, g_wah);
    cudaGetSymbolAddress((void**)&wal, g_wal);
    cudaGetSymbolAddress((void**)&wph, g_wph);
    cudaGetSymbolAddress((void**)&wpl, g_wpl);
    cudaGetSymbolAddress((void**)&yh,  g_yh);
    cudaGetSymbolAddress((void**)&yl,  g_yl);

    cudaFuncSetAttribute(mma_gemm_kernel,
                         cudaFuncAttributeMaxDynamicSharedMemorySize, 81920);
    cudaFuncSetAttribute(attn_mma_kernel,
                         cudaFuncAttributeMaxDynamicSharedMemorySize, 73728);

    // Pre-pass: split x, transpose+split weights
    split_bf16_kernel<<<4096, 256>>>(x, xh, xl, 4096 * 1024 / 4);
    transpose_split_kernel<<<dim3(3072 / 32, 1024 / 32), dim3(32, 8)>>>(
        w_attn, wah, wal, 1024, 3072);
    transpose_split_kernel<<<dim3(1024 / 32, 1024 / 32), dim3(32, 8)>>>(
        w_proj, wph, wpl, 1024, 1024);

    // 1) qkv = x @ w_attn + b_attn  -> hi/lo bf16 directly
    mma_gemm_kernel<<<dim3(4096 / 128, 3072 / 128), 256, 81920>>>(
        xh, xl, wah, wal, b_attn, nullptr, qkvh, qkvl, 4096, 3072, 1024);

    // 2) causal attention -> yh/yl (bf16 in, bf16 out)
    attn_mma_kernel<<<dim3(2048 / 128, 16, 2), 256, 73728>>>(qkvh, qkvl, yh, yl);

    // 3) out = y @ w_proj + b_proj  (fp32 out)
    mma_gemm_kernel<<<dim3(4096 / 128, 1024 / 128), 256, 81920>>>(
        yh, yl, wph, wpl, b_proj, out, nullptr, nullptr, 4096, 1024, 1024);
}